// round 2
// baseline (speedup 1.0000x reference)
#include <cuda_runtime.h>
#include <cuda_bf16.h>
#include <cstdint>

#define E_ 16
#define B_ 32768
#define L_ 128
#define H_ 64
#define C_ 10
#define TPB 128

// ---------------- device scratch (no allocations allowed) ----------------
__device__ int g_counts[E_];
__device__ int g_bucket[E_ * B_];
__device__ int g_flag;   // 1 => mask elements are 1 byte; 0 => 4 bytes

// ---------------- kernel 1: mask dtype detect + counter reset ----------------
// Reads only the first 16KB of the mask buffer. Logical element count is
// E*B = 512K, so the buffer is >= 512KB even for 1-byte dtype: always in-bounds.
//   bool/int8 one-hot: ~1/16 of bytes are exactly 1 -> ~1024 hits in 16384.
//   int32 one-hot:     ~1/64 of bytes -> ~256 hits.
//   float32 one-hot:   1.0f = {00,00,80,3F} -> 0 hits.
// Threshold 512 separates the 1-byte case from both 4-byte cases.
__global__ void k_detect(const unsigned char* __restrict__ m) {
    __shared__ int s[256];
    int t = threadIdx.x;
    int c = 0;
    for (int i = t; i < 16384; i += 256) c += (m[i] == 1);
    s[t] = c;
    __syncthreads();
    for (int o = 128; o > 0; o >>= 1) {
        if (t < o) s[t] += s[t + o];
        __syncthreads();
    }
    if (t == 0) g_flag = (s[0] > 512) ? 1 : 0;
    if (t < E_) g_counts[t] = 0;
}

// ---------------- kernel 2: route tokens into per-expert buckets ----------------
// Output logits per token depend only on (token, its expert), so the
// nondeterministic bucket ordering from atomics does not affect d_out.
__global__ void k_assign(const void* __restrict__ mask) {
    int b = blockIdx.x * 256 + threadIdx.x;
    if (b >= B_) return;
    int ef = 0;
    if (g_flag) {
        const unsigned char* m = (const unsigned char*)mask;
        #pragma unroll
        for (int e = 0; e < E_; e++) {
            if (m[(size_t)e * B_ + b]) { ef = e; break; }
        }
    } else {
        const unsigned int* m = (const unsigned int*)mask;  // int32 or float32: any nonzero bits
        #pragma unroll
        for (int e = 0; e < E_; e++) {
            if (m[(size_t)e * B_ + b]) { ef = e; break; }
        }
    }
    int pos = atomicAdd(&g_counts[ef], 1);
    g_bucket[ef * B_ + pos] = b;
}

// ---------------- kernel 3: per-expert 3-layer MLP ----------------
// grid = (256 chunks, 16 experts); blocks past their expert's token count
// exit after one LDG. Expert weights staged in dynamic smem (broadcast LDS);
// per-token hidden activations staged through padded smem rows.
__global__ void __launch_bounds__(TPB, 1) k_mlp(
    const float* __restrict__ latent,
    const float* __restrict__ W1, const float* __restrict__ b1,
    const float* __restrict__ W2, const float* __restrict__ b2,
    const float* __restrict__ W3, const float* __restrict__ b3,
    float* __restrict__ out)
{
    const int e = blockIdx.y;
    const int cnt = g_counts[e];
    const int base = blockIdx.x * TPB;
    if (base >= cnt) return;

    extern __shared__ float sm[];
    float* sW1 = sm;               // 8192 floats  [128][64]
    float* sW2 = sW1 + L_ * H_;    // 4096 floats  [64][64]
    float* sW3 = sW2 + H_ * H_;    // 640 floats   [64][10]
    float* sb1 = sW3 + H_ * C_;    // 64
    float* sb2 = sb1 + H_;         // 64
    float* sb3 = sb2 + H_;         // 16 (padded)
    float* sH  = sb3 + 16;         // TPB rows x 65 (pad kills bank conflicts)

    const int t = threadIdx.x;
    {
        const float4* g1 = (const float4*)(W1 + (size_t)e * L_ * H_);
        float4* d1 = (float4*)sW1;
        #pragma unroll
        for (int i = 0; i < 16; i++) d1[t + i * TPB] = g1[t + i * TPB];
        const float4* g2 = (const float4*)(W2 + (size_t)e * H_ * H_);
        float4* d2 = (float4*)sW2;
        #pragma unroll
        for (int i = 0; i < 8; i++) d2[t + i * TPB] = g2[t + i * TPB];
        const float* g3 = W3 + (size_t)e * H_ * C_;
        #pragma unroll
        for (int i = 0; i < 5; i++) sW3[t + i * TPB] = g3[t + i * TPB];
        if (t < H_) { sb1[t] = b1[e * H_ + t]; sb2[t] = b2[e * H_ + t]; }
        if (t < C_) sb3[t] = b3[e * C_ + t];
    }
    __syncthreads();

    const int idx = base + t;
    if (idx >= cnt) return;              // no block-wide syncs after this point
    const int token = g_bucket[e * B_ + idx];

    const float4* xr = (const float4*)(latent + ((size_t)e * B_ + (size_t)token) * L_);
    float* myH = sH + t * 65;

    float acc[H_];
    #pragma unroll
    for (int j = 0; j < H_; j++) acc[j] = sb1[j];

    // ---- layer 1: [128] x [128,64] ----
    for (int k4 = 0; k4 < L_ / 4; k4++) {
        float4 xv = xr[k4];
        float xs[4] = {xv.x, xv.y, xv.z, xv.w};
        const float* wr = sW1 + (k4 * 4) * H_;
        #pragma unroll
        for (int kk = 0; kk < 4; kk++) {
            float x = xs[kk];
            const float4* w4 = (const float4*)(wr + kk * H_);
            #pragma unroll
            for (int j4 = 0; j4 < 16; j4++) {
                float4 w = w4[j4];
                acc[j4 * 4 + 0] += x * w.x;
                acc[j4 * 4 + 1] += x * w.y;
                acc[j4 * 4 + 2] += x * w.z;
                acc[j4 * 4 + 3] += x * w.w;
            }
        }
    }
    #pragma unroll
    for (int j = 0; j < H_; j++) myH[j] = fmaxf(acc[j], 0.0f);

    // ---- layer 2: [64] x [64,64] ----
    #pragma unroll
    for (int j = 0; j < H_; j++) acc[j] = sb2[j];
    for (int k = 0; k < H_; k++) {
        float x = myH[k];
        const float4* w4 = (const float4*)(sW2 + k * H_);
        #pragma unroll
        for (int j4 = 0; j4 < 16; j4++) {
            float4 w = w4[j4];
            acc[j4 * 4 + 0] += x * w.x;
            acc[j4 * 4 + 1] += x * w.y;
            acc[j4 * 4 + 2] += x * w.z;
            acc[j4 * 4 + 3] += x * w.w;
        }
    }
    #pragma unroll
    for (int j = 0; j < H_; j++) myH[j] = fmaxf(acc[j], 0.0f);

    // ---- layer 3: [64] x [64,10] ----
    float o[C_];
    #pragma unroll
    for (int c = 0; c < C_; c++) o[c] = sb3[c];
    for (int k = 0; k < H_; k++) {
        float x = myH[k];
        const float* w = sW3 + k * C_;
        #pragma unroll
        for (int c = 0; c < C_; c++) o[c] += x * w[c];
    }

    float2* po = (float2*)(out + (size_t)token * C_);   // token*40B is 8-byte aligned
    po[0] = make_float2(o[0], o[1]);
    po[1] = make_float2(o[2], o[3]);
    po[2] = make_float2(o[4], o[5]);
    po[3] = make_float2(o[6], o[7]);
    po[4] = make_float2(o[8], o[9]);
}

// ---------------- launch ----------------
extern "C" void kernel_launch(void* const* d_in, const int* in_sizes, int n_in,
                              void* d_out, int out_size) {
    // metadata order: x, mask, latent, W1, b1, W2, b2, W3, b3
    const void*  mask   = d_in[1];
    const float* latent = (const float*)d_in[2];
    const float* W1     = (const float*)d_in[3];
    const float* b1     = (const float*)d_in[4];
    const float* W2     = (const float*)d_in[5];
    const float* b2     = (const float*)d_in[6];
    const float* W3     = (const float*)d_in[7];
    const float* b3     = (const float*)d_in[8];
    float* out = (float*)d_out;

    const size_t smem_bytes =
        (size_t)(L_ * H_ + H_ * H_ + H_ * C_ + H_ + H_ + 16 + TPB * 65) * sizeof(float);
    cudaFuncSetAttribute(k_mlp, cudaFuncAttributeMaxDynamicSharedMemorySize, (int)smem_bytes);

    k_detect<<<1, 256>>>((const unsigned char*)mask);
    k_assign<<<B_ / 256, 256>>>(mask);
    k_mlp<<<dim3(B_ / TPB, E_), TPB, smem_bytes>>>(latent, W1, b1, W2, b2, W3, b3, out);
}

// round 4
// speedup vs baseline: 1.1912x; 1.1912x over previous
#include <cuda_runtime.h>
#include <cuda_bf16.h>
#include <cstdint>

#define E_ 16
#define B_ 32768
#define L_ 128
#define H_ 64
#define C_ 10
#define TPB 128          // threads per block in k_mlp
#define TOKB 256         // tokens per block (2 per thread)

typedef unsigned long long u64;

// ---------------- device scratch ----------------
__device__ int g_counts[E_];
__device__ int g_bucket[E_ * B_];
__device__ int g_flag;   // 1 => mask is 1-byte elements; 0 => 4-byte

// ---------------- packed f32x2 helpers (sm_103a) ----------------
__device__ __forceinline__ u64 pk2(float a, float b) {
    u64 r; asm("mov.b64 %0, {%1, %2};" : "=l"(r) : "f"(a), "f"(b)); return r;
}
__device__ __forceinline__ void unpk2(float& a, float& b, u64 v) {
    asm("mov.b64 {%0, %1}, %2;" : "=f"(a), "=f"(b) : "l"(v));
}
__device__ __forceinline__ void fma2(u64& d, u64 a, u64 b) {
    asm("fma.rn.f32x2 %0, %1, %2, %0;" : "+l"(d) : "l"(a), "l"(b));
}
__device__ __forceinline__ void lds2x64(u64& a, u64& b, unsigned addr) {
    asm volatile("ld.shared.v2.b64 {%0, %1}, [%2];" : "=l"(a), "=l"(b) : "r"(addr));
}
__device__ __forceinline__ u64 lds64(unsigned addr) {
    u64 r; asm volatile("ld.shared.b64 %0, [%1];" : "=l"(r) : "r"(addr)); return r;
}
__device__ __forceinline__ float lds32(unsigned addr) {
    float r; asm volatile("ld.shared.b32 %0, [%1];" : "=f"(r) : "r"(addr)); return r;
}
__device__ __forceinline__ void sts64(unsigned addr, u64 v) {
    asm volatile("st.shared.b64 [%0], %1;" :: "r"(addr), "l"(v));
}
__device__ __forceinline__ u64 relu2(u64 v) {
    float lo, hi; unpk2(lo, hi, v);
    return pk2(fmaxf(lo, 0.f), fmaxf(hi, 0.f));
}

// ---------------- kernel 1: mask dtype detect + zero counters ----------------
// Scans first 4096 bytes (buffer >= 512KB for any dtype: always in-bounds).
//   1-byte one-hot: ~4096/16 = 256 bytes equal to 1
//   int32 one-hot:  1024 ints, ~64 low bytes equal to 1
//   float32:        1.0f bytes {00,00,80,3F} -> 0
// Threshold 128 separates the 1-byte case from both 4-byte cases.
__global__ void k_detect(const unsigned char* __restrict__ m) {
    int t = threadIdx.x;                   // 128 threads
    const uchar4* m4 = (const uchar4*)m;
    int c = 0;
    #pragma unroll
    for (int i = 0; i < 8; i++) {
        uchar4 v = m4[t + i * 128];
        c += (v.x == 1) + (v.y == 1) + (v.z == 1) + (v.w == 1);
    }
    #pragma unroll
    for (int o = 16; o; o >>= 1) c += __shfl_xor_sync(0xFFFFFFFFu, c, o);
    __shared__ int ws[4];
    if ((t & 31) == 0) ws[t >> 5] = c;
    __syncthreads();
    if (t == 0) g_flag = (ws[0] + ws[1] + ws[2] + ws[3]) > 128;
    if (t < E_) g_counts[t] = 0;
}

// ---------------- kernel 2: route tokens into per-expert buckets ----------------
// Per-token output depends only on (token, expert); atomic ordering inside a
// bucket does not affect d_out.
__global__ void k_assign(const void* __restrict__ mask) {
    int b = blockIdx.x * 256 + threadIdx.x;
    if (b >= B_) return;
    int ef = 0;
    if (g_flag) {
        const unsigned char* m = (const unsigned char*)mask;
        #pragma unroll
        for (int e = 0; e < E_; e++)
            if (m[(size_t)e * B_ + b]) { ef = e; break; }
    } else {
        const unsigned int* m = (const unsigned int*)mask;  // int32 or f32 bits
        #pragma unroll
        for (int e = 0; e < E_; e++)
            if (m[(size_t)e * B_ + b]) { ef = e; break; }
    }
    int pos = atomicAdd(&g_counts[ef], 1);
    g_bucket[ef * B_ + pos] = b;
}

// ---------------- smem layout (floats) ----------------
#define OFF_W1 0
#define OFF_W2 (L_ * H_)                       // 8192
#define OFF_W3 (OFF_W2 + H_ * H_)              // 12288
#define OFF_B1 (OFF_W3 + H_ * C_)              // 12928
#define OFF_B2 (OFF_B1 + H_)                   // 12992
#define OFF_B3 (OFF_B2 + H_)                   // 13056
#define OFF_H  (OFF_B3 + 16)                   // 13072
#define HPAD   66                              // even pad: b64-aligned rows, no conflicts
#define SMEM_FLOATS (OFF_H + TOKB * HPAD)      // 29968 floats = 119872 B

// ---------------- kernel 3: per-expert MLP, f32x2-packed, 2 tokens/thread ----------------
__global__ void __launch_bounds__(TPB, 1) k_mlp(
    const float* __restrict__ latent,
    const float* __restrict__ W1, const float* __restrict__ b1,
    const float* __restrict__ W2, const float* __restrict__ b2,
    const float* __restrict__ W3, const float* __restrict__ b3,
    float* __restrict__ out)
{
    const int e   = blockIdx.y;
    const int cnt = g_counts[e];
    const int base = blockIdx.x * TOKB;
    if (base >= cnt) return;

    extern __shared__ float sm[];
    const int t = threadIdx.x;

    // ---- stage weights/biases ----
    {
        const float4* g1 = (const float4*)(W1 + (size_t)e * L_ * H_);
        float4* d1 = (float4*)(sm + OFF_W1);
        #pragma unroll
        for (int i = 0; i < 16; i++) d1[t + i * TPB] = g1[t + i * TPB];
        const float4* g2 = (const float4*)(W2 + (size_t)e * H_ * H_);
        float4* d2 = (float4*)(sm + OFF_W2);
        #pragma unroll
        for (int i = 0; i < 8; i++) d2[t + i * TPB] = g2[t + i * TPB];
        const float* g3 = W3 + (size_t)e * H_ * C_;
        #pragma unroll
        for (int i = 0; i < 5; i++) sm[OFF_W3 + t + i * TPB] = g3[t + i * TPB];
        if (t < H_) { sm[OFF_B1 + t] = b1[e * H_ + t]; sm[OFF_B2 + t] = b2[e * H_ + t]; }
        if (t < C_) sm[OFF_B3 + t] = b3[e * C_ + t];
    }
    __syncthreads();

    const int idx0 = base + t;
    const int idx1 = base + TPB + t;
    const bool v0 = idx0 < cnt;
    const bool v1 = idx1 < cnt;
    if (!v0) return;   // idx1 > idx0 is also invalid; no block syncs below
    // invalid idx1: bucket slot is zero-init or stale-valid token id -> in-bounds read
    const int tok0 = g_bucket[e * B_ + idx0];
    const int tok1 = g_bucket[e * B_ + (v1 ? idx1 : idx0)];

    const unsigned smb = (unsigned)__cvta_generic_to_shared(sm);
    const unsigned aW1 = smb + OFF_W1 * 4;
    const unsigned aW2 = smb + OFF_W2 * 4;
    const unsigned aW3 = smb + OFF_W3 * 4;
    const unsigned aB1 = smb + OFF_B1 * 4;
    const unsigned aB2 = smb + OFF_B2 * 4;
    const unsigned aB3 = smb + OFF_B3 * 4;
    const unsigned aH0 = smb + (OFF_H + t * HPAD) * 4;
    const unsigned aH1 = smb + (OFF_H + (t + TPB) * HPAD) * 4;

    const float4* x0 = (const float4*)(latent + ((size_t)e * B_ + (size_t)tok0) * L_);
    const float4* x1 = (const float4*)(latent + ((size_t)e * B_ + (size_t)tok1) * L_);

    u64 a0[H_ / 2], a1[H_ / 2];

    // ======== layer 1: [128] x [128,64] ========
    #pragma unroll
    for (int j = 0; j < H_ / 2; j++) { a0[j] = lds64(aB1 + j * 8); a1[j] = a0[j]; }
    for (int k4 = 0; k4 < L_ / 4; k4++) {
        float4 xv0 = x0[k4];
        float4 xv1 = x1[k4];
        float xs0[4] = {xv0.x, xv0.y, xv0.z, xv0.w};
        float xs1[4] = {xv1.x, xv1.y, xv1.z, xv1.w};
        #pragma unroll
        for (int kk = 0; kk < 4; kk++) {
            u64 xx0 = pk2(xs0[kk], xs0[kk]);
            u64 xx1 = pk2(xs1[kk], xs1[kk]);
            unsigned row = aW1 + (unsigned)((k4 * 4 + kk) * H_) * 4;
            #pragma unroll
            for (int p = 0; p < 16; p++) {
                u64 wa, wb;
                lds2x64(wa, wb, row + p * 16);
                fma2(a0[2 * p],     xx0, wa);
                fma2(a0[2 * p + 1], xx0, wb);
                fma2(a1[2 * p],     xx1, wa);
                fma2(a1[2 * p + 1], xx1, wb);
            }
        }
    }
    #pragma unroll
    for (int j = 0; j < H_ / 2; j++) {
        sts64(aH0 + j * 8, relu2(a0[j]));
        sts64(aH1 + j * 8, relu2(a1[j]));
    }

    // ======== layer 2: [64] x [64,64] ========
    #pragma unroll
    for (int j = 0; j < H_ / 2; j++) { a0[j] = lds64(aB2 + j * 8); a1[j] = a0[j]; }
    for (int k = 0; k < H_; k++) {
        float h0 = lds32(aH0 + k * 4);
        float h1 = lds32(aH1 + k * 4);
        u64 xx0 = pk2(h0, h0);
        u64 xx1 = pk2(h1, h1);
        unsigned row = aW2 + (unsigned)(k * H_) * 4;
        #pragma unroll
        for (int p = 0; p < 16; p++) {
            u64 wa, wb;
            lds2x64(wa, wb, row + p * 16);
            fma2(a0[2 * p],     xx0, wa);
            fma2(a0[2 * p + 1], xx0, wb);
            fma2(a1[2 * p],     xx1, wa);
            fma2(a1[2 * p + 1], xx1, wb);
        }
    }
    #pragma unroll
    for (int j = 0; j < H_ / 2; j++) {
        sts64(aH0 + j * 8, relu2(a0[j]));
        sts64(aH1 + j * 8, relu2(a1[j]));
    }

    // ======== layer 3: [64] x [64,10] ========
    u64 o0[C_ / 2], o1[C_ / 2];
    #pragma unroll
    for (int c = 0; c < C_ / 2; c++) { o0[c] = lds64(aB3 + c * 8); o1[c] = o0[c]; }
    for (int k = 0; k < H_; k++) {
        float h0 = lds32(aH0 + k * 4);
        float h1 = lds32(aH1 + k * 4);
        u64 xx0 = pk2(h0, h0);
        u64 xx1 = pk2(h1, h1);
        unsigned row = aW3 + (unsigned)(k * C_) * 4;   // k*40 bytes, 8-aligned
        #pragma unroll
        for (int c = 0; c < C_ / 2; c++) {
            u64 w = lds64(row + c * 8);
            fma2(o0[c], xx0, w);
            fma2(o1[c], xx1, w);
        }
    }

    {
        float2* po = (float2*)(out + (size_t)tok0 * C_);
        #pragma unroll
        for (int c = 0; c < C_ / 2; c++) {
            float lo, hi; unpk2(lo, hi, o0[c]);
            po[c] = make_float2(lo, hi);
        }
    }
    if (v1) {
        float2* po = (float2*)(out + (size_t)tok1 * C_);
        #pragma unroll
        for (int c = 0; c < C_ / 2; c++) {
            float lo, hi; unpk2(lo, hi, o1[c]);
            po[c] = make_float2(lo, hi);
        }
    }
}

// ---------------- launch ----------------
extern "C" void kernel_launch(void* const* d_in, const int* in_sizes, int n_in,
                              void* d_out, int out_size) {
    // metadata order: x, mask, latent, W1, b1, W2, b2, W3, b3
    const void*  mask   = d_in[1];
    const float* latent = (const float*)d_in[2];
    const float* W1     = (const float*)d_in[3];
    const float* b1     = (const float*)d_in[4];
    const float* W2     = (const float*)d_in[5];
    const float* b2     = (const float*)d_in[6];
    const float* W3     = (const float*)d_in[7];
    const float* b3     = (const float*)d_in[8];
    float* out = (float*)d_out;

    const size_t smem_bytes = (size_t)SMEM_FLOATS * sizeof(float);
    cudaFuncSetAttribute(k_mlp, cudaFuncAttributeMaxDynamicSharedMemorySize, (int)smem_bytes);

    k_detect<<<1, 128>>>((const unsigned char*)mask);
    k_assign<<<B_ / 256, 256>>>(mask);
    k_mlp<<<dim3(B_ / TOKB, E_), TPB, smem_bytes>>>(latent, W1, b1, W2, b2, W3, b3, out);
}